// round 12
// baseline (speedup 1.0000x reference)
#include <cuda_runtime.h>
#include <math.h>

#define NG     4096
#define NB     16
#define SS     4
#define RES    64
#define RELAX  0.1875f             // (2/16)*1.5
#define STEP   (2.0f/63.0f)
#define LOG2E  1.4426950408889634f
#define NW     (NG/32)             // 128 mask words

__device__ __forceinline__ float ex2_fast(float x) {
    float y;
    asm("ex2.approx.ftz.f32 %0, %1;" : "=f"(y) : "f"(x));
    return y;
}

// ---- scratch ----
__device__ float4   g_par[NG * 3];          // (cx,cy,cz,w) (q0,q1,q2,q3) (q4,q5,_,_)
__device__ unsigned g_mask[3][NB][NW];      // per-axis, per-slot occupancy bitmask

// ============================================================
// Kernel A: 16 CTAs x 1024 thr. Redundant center/scale per CTA
// (front-batched loads), then threads 0..255 prep 256 gaussians
// and warps 0..7 emit mask words.  (unchanged — proven)
// ============================================================
__global__ void __launch_bounds__(1024) kA(const float* __restrict__ xyz,
                                           const float* __restrict__ scaling,
                                           const float* __restrict__ rot,
                                           const float* __restrict__ opac) {
    __shared__ float wmn[32][3], wmx[32][3];
    __shared__ float bc[4];
    const int t = threadIdx.x, lane = t & 31, wi = t >> 5;
    const int b = blockIdx.x;

    float ox[4], vx[4], vy[4], vz[4];
#pragma unroll
    for (int i = 0; i < 4; i++) {
        int g = i * 1024 + t;
        ox[i] = opac[g];
        vx[i] = xyz[3 * g];
        vy[i] = xyz[3 * g + 1];
        vz[i] = xyz[3 * g + 2];
    }
    float mn0 = 1e10f, mn1 = 1e10f, mn2 = 1e10f;
    float mx0 = -1e10f, mx1 = -1e10f, mx2 = -1e10f;
#pragma unroll
    for (int i = 0; i < 4; i++) {
        float s = 1.0f / (1.0f + __expf(-ox[i]));
        if (s > 0.005f) {
            mn0 = fminf(mn0, vx[i]); mn1 = fminf(mn1, vy[i]); mn2 = fminf(mn2, vz[i]);
            mx0 = fmaxf(mx0, vx[i]); mx1 = fmaxf(mx1, vy[i]); mx2 = fmaxf(mx2, vz[i]);
        }
    }
#pragma unroll
    for (int s = 16; s; s >>= 1) {
        mn0 = fminf(mn0, __shfl_xor_sync(0xffffffffu, mn0, s));
        mn1 = fminf(mn1, __shfl_xor_sync(0xffffffffu, mn1, s));
        mn2 = fminf(mn2, __shfl_xor_sync(0xffffffffu, mn2, s));
        mx0 = fmaxf(mx0, __shfl_xor_sync(0xffffffffu, mx0, s));
        mx1 = fmaxf(mx1, __shfl_xor_sync(0xffffffffu, mx1, s));
        mx2 = fmaxf(mx2, __shfl_xor_sync(0xffffffffu, mx2, s));
    }
    if (lane == 0) {
        wmn[wi][0] = mn0; wmn[wi][1] = mn1; wmn[wi][2] = mn2;
        wmx[wi][0] = mx0; wmx[wi][1] = mx1; wmx[wi][2] = mx2;
    }
    __syncthreads();
    if (wi == 0) {
        float a0 = wmn[lane][0], a1 = wmn[lane][1], a2 = wmn[lane][2];
        float b0 = wmx[lane][0], b1 = wmx[lane][1], b2 = wmx[lane][2];
#pragma unroll
        for (int s = 16; s; s >>= 1) {
            a0 = fminf(a0, __shfl_xor_sync(0xffffffffu, a0, s));
            a1 = fminf(a1, __shfl_xor_sync(0xffffffffu, a1, s));
            a2 = fminf(a2, __shfl_xor_sync(0xffffffffu, a2, s));
            b0 = fmaxf(b0, __shfl_xor_sync(0xffffffffu, b0, s));
            b1 = fmaxf(b1, __shfl_xor_sync(0xffffffffu, b1, s));
            b2 = fmaxf(b2, __shfl_xor_sync(0xffffffffu, b2, s));
        }
        if (lane == 0) {
            bc[0] = (a0 + b0) * 0.5f;
            bc[1] = (a1 + b1) * 0.5f;
            bc[2] = (a2 + b2) * 0.5f;
            bc[3] = 1.8f / fmaxf(fmaxf(b0 - a0, b1 - a1), b2 - a2);
        }
    }
    __syncthreads();
    if (t >= 256) return;

    const float cx = bc[0], cy = bc[1], cz = bc[2], sc = bc[3];

    const int g = b * 256 + t;
    float gx = (xyz[3 * g]     - cx) * sc;
    float gy = (xyz[3 * g + 1] - cy) * sc;
    float gz = (xyz[3 * g + 2] - cz) * sc;
    float o  = opac[g];
    float sig = 1.0f / (1.0f + __expf(-o));
    float w  = (sig > 0.005f) ? sig : 0.0f;

    float s0 = __expf(scaling[3 * g])     * sc;
    float s1 = __expf(scaling[3 * g + 1]) * sc;
    float s2 = __expf(scaling[3 * g + 2]) * sc;

    float r = rot[4 * g], x = rot[4 * g + 1], y = rot[4 * g + 2], z = rot[4 * g + 3];
    float rn = 1.0f / sqrtf(r * r + x * x + y * y + z * z);
    r *= rn; x *= rn; y *= rn; z *= rn;

    float R00 = 1.0f - 2.0f * (y * y + z * z);
    float R01 = 2.0f * (x * y - r * z);
    float R02 = 2.0f * (x * z + r * y);
    float R10 = 2.0f * (x * y + r * z);
    float R11 = 1.0f - 2.0f * (x * x + z * z);
    float R12 = 2.0f * (y * z - r * x);
    float R20 = 2.0f * (x * z - r * y);
    float R21 = 2.0f * (y * z + r * x);
    float R22 = 1.0f - 2.0f * (x * x + y * y);

    float L00 = R00 * s0, L01 = R01 * s1, L02 = R02 * s2;
    float L10 = R10 * s0, L11 = R11 * s1, L12 = R12 * s2;
    float L20 = R20 * s0, L21 = R21 * s1, L22 = R22 * s2;

    float a  = L00 * L00 + L01 * L01 + L02 * L02;
    float bb = L00 * L10 + L01 * L11 + L02 * L12;
    float c  = L00 * L20 + L01 * L21 + L02 * L22;
    float d  = L10 * L10 + L11 * L11 + L12 * L12;
    float e  = L10 * L20 + L11 * L21 + L12 * L22;
    float f  = L20 * L20 + L21 * L21 + L22 * L22;

    float det = a * d * f + 2.0f * e * c * bb - e * e * a - c * c * d - bb * bb * f + 1e-24f;
    float id  = 1.0f / det;
    float q0 = (d * f - e * e)   * id * (-0.5f * LOG2E);
    float q1 = (e * c - bb * f)  * id * (-LOG2E);
    float q2 = (e * bb - c * d)  * id * (-LOG2E);
    float q3 = (a * f - c * c)   * id * (-0.5f * LOG2E);
    float q4 = (bb * c - e * a)  * id * (-LOG2E);
    float q5 = (a * d - bb * bb) * id * (-0.5f * LOG2E);

    g_par[3 * g]     = make_float4(gx, gy, gz, w);
    g_par[3 * g + 1] = make_float4(q0, q1, q2, q3);
    g_par[3 * g + 2] = make_float4(q4, q5, 0.0f, 0.0f);

    const int word = b * 8 + wi;
#pragma unroll 1
    for (int s = 0; s < 16; s++) {
        float lo = -1.0f + STEP * (float)(s * SS)          - RELAX;
        float hi = -1.0f + STEP * (float)(s * SS + SS - 1) + RELAX;
        unsigned bx = __ballot_sync(0xffffffffu, (w > 0.0f) && (gx > lo) && (gx < hi));
        unsigned by = __ballot_sync(0xffffffffu, (gy > lo) && (gy < hi));
        unsigned bz = __ballot_sync(0xffffffffu, (gz > lo) && (gz < hi));
        if (lane == 0) {
            g_mask[0][s][word] = bx;
            g_mask[1][s][word] = by;
            g_mask[2][s][word] = bz;
        }
    }
}

// ============================================================
// Kernel B: one CTA per 4x4x4 block, 256 threads.
// Compaction: warp 0 only — uint4 mask loads, warp-local scan,
// scatter of pre-multiplied byte offsets (g*48), ONE barrier.
// Eval: 16 xy-columns x 16 splits, incremental-dz quadratic.
// Epilogue: shfl_xor(16) + 8-way smem reduce.
// ============================================================
__global__ void __launch_bounds__(256, 8) kmain(float* __restrict__ out) {
    __shared__ unsigned list[NG];         // 16 KB, holds g*48 byte offsets
    __shared__ float red[8][64];          // 2 KB  [warp][point]
    __shared__ int   s_cnt;

    const int b  = (blockIdx.x * 1357) & 4095;   // bijective scramble
    const int bi = b >> 8, bj = (b >> 4) & 15, bk = b & 15;
    const int t  = threadIdx.x, lane = t & 31, wi = t >> 5;

    // ---- warp-0 compaction: 4 mask words per lane via uint4 ----
    if (wi == 0) {
        const uint4* r0 = reinterpret_cast<const uint4*>(g_mask[0][bi]);
        const uint4* r1 = reinterpret_cast<const uint4*>(g_mask[1][bj]);
        const uint4* r2 = reinterpret_cast<const uint4*>(g_mask[2][bk]);
        uint4 mx = r0[lane], my = r1[lane], mz = r2[lane];
        unsigned w0 = mx.x & my.x & mz.x;
        unsigned w1 = mx.y & my.y & mz.y;
        unsigned w2 = mx.z & my.z & mz.z;
        unsigned w3 = mx.w & my.w & mz.w;
        int lc = __popc(w0) + __popc(w1) + __popc(w2) + __popc(w3);
        int inc = lc;
#pragma unroll
        for (int s = 1; s < 32; s <<= 1) {
            int v = __shfl_up_sync(0xffffffffu, inc, s);
            if (lane >= s) inc += v;
        }
        int off = inc - lc;
        unsigned gb = (unsigned)lane * 128u;
        unsigned wds[4] = {w0, w1, w2, w3};
#pragma unroll
        for (int k = 0; k < 4; k++) {
            unsigned mm = wds[k];
            unsigned kb = gb + (unsigned)k * 32u;
            while (mm) {
                int bp = __ffs(mm) - 1;
                mm &= mm - 1;
                list[off++] = (kb + (unsigned)bp) * 48u;
            }
        }
        if (lane == 31) s_cnt = inc;
    }
    __syncthreads();
    const int cnt = s_cnt;

    if (cnt == 0) {
        if (t < 64) {
            int oi = t >> 4, oj = (t >> 2) & 3, ok = t & 3;
            out[((bi * SS + oi) * RES + (bj * SS + oj)) * RES + (bk * SS + ok)] = 0.0f;
        }
        return;
    }

    // thread role: column (x,y) + split id
    const int col = lane & 15;             // 0..15
    const int h   = lane >> 4;             // half-warp
    const int sid = wi * 2 + h;            // split 0..15
    const int oi  = col >> 2, oj = col & 3;

    const float px  = -1.0f + STEP * (float)(bi * SS + oi);
    const float py  = -1.0f + STEP * (float)(bj * SS + oj);
    const float pz0 = -1.0f + STEP * (float)(bk * SS);

    const char* __restrict__ parb = (const char*)g_par;

    float ac0 = 0.0f, ac1 = 0.0f, ac2 = 0.0f, ac3 = 0.0f;

#pragma unroll 2
    for (int j = sid; j < cnt; j += 16) {
        unsigned off = list[j];
        float4 A = *reinterpret_cast<const float4*>(parb + off);
        float4 B = *reinterpret_cast<const float4*>(parb + off + 16);
        float4 C = *reinterpret_cast<const float4*>(parb + off + 32);
        float dx = px - A.x, dy = py - A.y;
        // c0 = q0*dx^2 + q1*dx*dy + q3*dy^2 ; c1 = q2*dx + q4*dy ; c2 = q5
        float t0 = fmaf(B.y, dy, B.x * dx);
        float c0 = fmaf(B.w * dy, dy, dx * t0);
        float c1 = fmaf(C.x, dy, B.z * dx);
        float c2 = C.y;
        float w  = A.w;

        float dz = pz0 - A.z;
        float p  = fmaf(fmaf(c2, dz, c1), dz, c0);
        if (p <= 0.0f) ac0 = fmaf(w, ex2_fast(p), ac0);
        dz += STEP;
        p = fmaf(fmaf(c2, dz, c1), dz, c0);
        if (p <= 0.0f) ac1 = fmaf(w, ex2_fast(p), ac1);
        dz += STEP;
        p = fmaf(fmaf(c2, dz, c1), dz, c0);
        if (p <= 0.0f) ac2 = fmaf(w, ex2_fast(p), ac2);
        dz += STEP;
        p = fmaf(fmaf(c2, dz, c1), dz, c0);
        if (p <= 0.0f) ac3 = fmaf(w, ex2_fast(p), ac3);
    }

    // combine the two splits (h=0,1) sharing a column within each warp
    ac0 += __shfl_xor_sync(0xffffffffu, ac0, 16);
    ac1 += __shfl_xor_sync(0xffffffffu, ac1, 16);
    ac2 += __shfl_xor_sync(0xffffffffu, ac2, 16);
    ac3 += __shfl_xor_sync(0xffffffffu, ac3, 16);

    if (lane < 16)   // lanes 0..15 hold the warp's per-column partials
        *reinterpret_cast<float4*>(&red[wi][col * 4]) = make_float4(ac0, ac1, ac2, ac3);
    __syncthreads();

    if (t < 64) {
        float s = 0.0f;
#pragma unroll
        for (int k = 0; k < 8; k++) s += red[k][t];
        int oi2 = t >> 4, oj2 = (t >> 2) & 3, ok2 = t & 3;
        out[((bi * SS + oi2) * RES + (bj * SS + oj2)) * RES + (bk * SS + ok2)] = s;
    }
}

// ============================================================
extern "C" void kernel_launch(void* const* d_in, const int* in_sizes, int n_in,
                              void* d_out, int out_size) {
    const float* xyz     = (const float*)d_in[0];
    const float* scaling = (const float*)d_in[1];
    const float* rot     = (const float*)d_in[2];
    const float* opac    = (const float*)d_in[3];
    float* out = (float*)d_out;

    kA<<<16, 1024>>>(xyz, scaling, rot, opac);
    kmain<<<NB * NB * NB, 256>>>(out);
}

// round 13
// speedup vs baseline: 1.0383x; 1.0383x over previous
#include <cuda_runtime.h>
#include <math.h>

#define NG     4096
#define NB     16
#define SS     4
#define RES    64
#define RELAX  0.1875f             // (2/16)*1.5
#define STEP   (2.0f/63.0f)
#define LOG2E  1.4426950408889634f
#define NW     (NG/32)             // 128 mask words

__device__ __forceinline__ float ex2_fast(float x) {
    float y;
    asm("ex2.approx.ftz.f32 %0, %1;" : "=f"(y) : "f"(x));
    return y;
}

// ---- scratch ----
__device__ float4   g_par[NG * 3];          // (cx,cy,cz,w) (q0,q1,q2,q3) (q4,q5,_,_)
__device__ unsigned g_mask[3][NB][NW];      // per-axis, per-slot occupancy bitmask

// ============================================================
// Kernel A: 16 CTAs x 1024 thr. Redundant center/scale per CTA
// (front-batched loads), then threads 0..255 prep 256 gaussians
// and warps 0..7 emit mask words.  (unchanged — proven)
// ============================================================
__global__ void __launch_bounds__(1024) kA(const float* __restrict__ xyz,
                                           const float* __restrict__ scaling,
                                           const float* __restrict__ rot,
                                           const float* __restrict__ opac) {
    __shared__ float wmn[32][3], wmx[32][3];
    __shared__ float bc[4];
    const int t = threadIdx.x, lane = t & 31, wi = t >> 5;
    const int b = blockIdx.x;

    float ox[4], vx[4], vy[4], vz[4];
#pragma unroll
    for (int i = 0; i < 4; i++) {
        int g = i * 1024 + t;
        ox[i] = opac[g];
        vx[i] = xyz[3 * g];
        vy[i] = xyz[3 * g + 1];
        vz[i] = xyz[3 * g + 2];
    }
    float mn0 = 1e10f, mn1 = 1e10f, mn2 = 1e10f;
    float mx0 = -1e10f, mx1 = -1e10f, mx2 = -1e10f;
#pragma unroll
    for (int i = 0; i < 4; i++) {
        float s = 1.0f / (1.0f + __expf(-ox[i]));
        if (s > 0.005f) {
            mn0 = fminf(mn0, vx[i]); mn1 = fminf(mn1, vy[i]); mn2 = fminf(mn2, vz[i]);
            mx0 = fmaxf(mx0, vx[i]); mx1 = fmaxf(mx1, vy[i]); mx2 = fmaxf(mx2, vz[i]);
        }
    }
#pragma unroll
    for (int s = 16; s; s >>= 1) {
        mn0 = fminf(mn0, __shfl_xor_sync(0xffffffffu, mn0, s));
        mn1 = fminf(mn1, __shfl_xor_sync(0xffffffffu, mn1, s));
        mn2 = fminf(mn2, __shfl_xor_sync(0xffffffffu, mn2, s));
        mx0 = fmaxf(mx0, __shfl_xor_sync(0xffffffffu, mx0, s));
        mx1 = fmaxf(mx1, __shfl_xor_sync(0xffffffffu, mx1, s));
        mx2 = fmaxf(mx2, __shfl_xor_sync(0xffffffffu, mx2, s));
    }
    if (lane == 0) {
        wmn[wi][0] = mn0; wmn[wi][1] = mn1; wmn[wi][2] = mn2;
        wmx[wi][0] = mx0; wmx[wi][1] = mx1; wmx[wi][2] = mx2;
    }
    __syncthreads();
    if (wi == 0) {
        float a0 = wmn[lane][0], a1 = wmn[lane][1], a2 = wmn[lane][2];
        float b0 = wmx[lane][0], b1 = wmx[lane][1], b2 = wmx[lane][2];
#pragma unroll
        for (int s = 16; s; s >>= 1) {
            a0 = fminf(a0, __shfl_xor_sync(0xffffffffu, a0, s));
            a1 = fminf(a1, __shfl_xor_sync(0xffffffffu, a1, s));
            a2 = fminf(a2, __shfl_xor_sync(0xffffffffu, a2, s));
            b0 = fmaxf(b0, __shfl_xor_sync(0xffffffffu, b0, s));
            b1 = fmaxf(b1, __shfl_xor_sync(0xffffffffu, b1, s));
            b2 = fmaxf(b2, __shfl_xor_sync(0xffffffffu, b2, s));
        }
        if (lane == 0) {
            bc[0] = (a0 + b0) * 0.5f;
            bc[1] = (a1 + b1) * 0.5f;
            bc[2] = (a2 + b2) * 0.5f;
            bc[3] = 1.8f / fmaxf(fmaxf(b0 - a0, b1 - a1), b2 - a2);
        }
    }
    __syncthreads();
    if (t >= 256) return;

    const float cx = bc[0], cy = bc[1], cz = bc[2], sc = bc[3];

    const int g = b * 256 + t;
    float gx = (xyz[3 * g]     - cx) * sc;
    float gy = (xyz[3 * g + 1] - cy) * sc;
    float gz = (xyz[3 * g + 2] - cz) * sc;
    float o  = opac[g];
    float sig = 1.0f / (1.0f + __expf(-o));
    float w  = (sig > 0.005f) ? sig : 0.0f;

    float s0 = __expf(scaling[3 * g])     * sc;
    float s1 = __expf(scaling[3 * g + 1]) * sc;
    float s2 = __expf(scaling[3 * g + 2]) * sc;

    float r = rot[4 * g], x = rot[4 * g + 1], y = rot[4 * g + 2], z = rot[4 * g + 3];
    float rn = 1.0f / sqrtf(r * r + x * x + y * y + z * z);
    r *= rn; x *= rn; y *= rn; z *= rn;

    float R00 = 1.0f - 2.0f * (y * y + z * z);
    float R01 = 2.0f * (x * y - r * z);
    float R02 = 2.0f * (x * z + r * y);
    float R10 = 2.0f * (x * y + r * z);
    float R11 = 1.0f - 2.0f * (x * x + z * z);
    float R12 = 2.0f * (y * z - r * x);
    float R20 = 2.0f * (x * z - r * y);
    float R21 = 2.0f * (y * z + r * x);
    float R22 = 1.0f - 2.0f * (x * x + y * y);

    float L00 = R00 * s0, L01 = R01 * s1, L02 = R02 * s2;
    float L10 = R10 * s0, L11 = R11 * s1, L12 = R12 * s2;
    float L20 = R20 * s0, L21 = R21 * s1, L22 = R22 * s2;

    float a  = L00 * L00 + L01 * L01 + L02 * L02;
    float bb = L00 * L10 + L01 * L11 + L02 * L12;
    float c  = L00 * L20 + L01 * L21 + L02 * L22;
    float d  = L10 * L10 + L11 * L11 + L12 * L12;
    float e  = L10 * L20 + L11 * L21 + L12 * L22;
    float f  = L20 * L20 + L21 * L21 + L22 * L22;

    float det = a * d * f + 2.0f * e * c * bb - e * e * a - c * c * d - bb * bb * f + 1e-24f;
    float id  = 1.0f / det;
    float q0 = (d * f - e * e)   * id * (-0.5f * LOG2E);
    float q1 = (e * c - bb * f)  * id * (-LOG2E);
    float q2 = (e * bb - c * d)  * id * (-LOG2E);
    float q3 = (a * f - c * c)   * id * (-0.5f * LOG2E);
    float q4 = (bb * c - e * a)  * id * (-LOG2E);
    float q5 = (a * d - bb * bb) * id * (-0.5f * LOG2E);

    g_par[3 * g]     = make_float4(gx, gy, gz, w);
    g_par[3 * g + 1] = make_float4(q0, q1, q2, q3);
    g_par[3 * g + 2] = make_float4(q4, q5, 0.0f, 0.0f);

    const int word = b * 8 + wi;
#pragma unroll 1
    for (int s = 0; s < 16; s++) {
        float lo = -1.0f + STEP * (float)(s * SS)          - RELAX;
        float hi = -1.0f + STEP * (float)(s * SS + SS - 1) + RELAX;
        unsigned bx = __ballot_sync(0xffffffffu, (w > 0.0f) && (gx > lo) && (gx < hi));
        unsigned by = __ballot_sync(0xffffffffu, (gy > lo) && (gy < hi));
        unsigned bz = __ballot_sync(0xffffffffu, (gz > lo) && (gz < hi));
        if (lane == 0) {
            g_mask[0][s][word] = bx;
            g_mask[1][s][word] = by;
            g_mask[2][s][word] = bz;
        }
    }
}

// ============================================================
// Kernel B: one CTA per 4x4x4 block, 256 threads (round-11 form).
// Compaction: threads 0..127, 4-warp scan (parallel critical path).
// List holds pre-multiplied BYTE offsets (g*48) — fewer IMADs in
// the eval loop. Eval: 16 xy-cols x 16 splits, incremental-dz
// quadratic. Epilogue: shfl_xor(16) + 8-way smem reduce.
// ============================================================
__global__ void __launch_bounds__(256, 8) kmain(float* __restrict__ out) {
    __shared__ unsigned list[NG];         // 16 KB, holds g*48 byte offsets
    __shared__ float red[8][64];          // 2 KB  [warp][point]
    __shared__ int   wtot[4];

    const int b  = (blockIdx.x * 1357) & 4095;   // bijective scramble
    const int bi = b >> 8, bj = (b >> 4) & 15, bk = b & 15;
    const int t  = threadIdx.x, lane = t & 31, wi = t >> 5;

    // ---- mask AND + deterministic compaction (threads 0..127) ----
    unsigned m = 0; int lc = 0; int inc = 0;
    if (t < NW) {
        m  = g_mask[0][bi][t] & g_mask[1][bj][t] & g_mask[2][bk][t];
        lc = __popc(m);
        inc = lc;
#pragma unroll
        for (int s = 1; s < 32; s <<= 1) {
            int v = __shfl_up_sync(0xffffffffu, inc, s);
            if (lane >= s) inc += v;
        }
        if (lane == 31) wtot[wi] = inc;
    }
    __syncthreads();
    const int cnt = wtot[0] + wtot[1] + wtot[2] + wtot[3];   // all threads
    if (t < NW) {
        int base = 0;
#pragma unroll
        for (int k = 0; k < 3; k++) if (wi > k) base += wtot[k];
        int off = base + inc - lc;
        unsigned gb = (unsigned)t * 32u;
        unsigned mm = m;
        while (mm) {
            int bp = __ffs(mm) - 1;
            mm &= mm - 1;
            list[off++] = (gb + (unsigned)bp) * 48u;   // byte offset into g_par
        }
    }
    __syncthreads();

    if (cnt == 0) {
        if (t < 64) {
            int oi = t >> 4, oj = (t >> 2) & 3, ok = t & 3;
            out[((bi * SS + oi) * RES + (bj * SS + oj)) * RES + (bk * SS + ok)] = 0.0f;
        }
        return;
    }

    // thread role: column (x,y) + split id
    const int col = lane & 15;             // 0..15
    const int h   = lane >> 4;             // half-warp
    const int sid = wi * 2 + h;            // split 0..15
    const int oi  = col >> 2, oj = col & 3;

    const float px  = -1.0f + STEP * (float)(bi * SS + oi);
    const float py  = -1.0f + STEP * (float)(bj * SS + oj);
    const float pz0 = -1.0f + STEP * (float)(bk * SS);

    const char* __restrict__ parb = (const char*)g_par;

    float ac0 = 0.0f, ac1 = 0.0f, ac2 = 0.0f, ac3 = 0.0f;

#pragma unroll 2
    for (int j = sid; j < cnt; j += 16) {
        unsigned off = list[j];
        float4 A = *reinterpret_cast<const float4*>(parb + off);
        float4 B = *reinterpret_cast<const float4*>(parb + off + 16);
        float4 C = *reinterpret_cast<const float4*>(parb + off + 32);
        float dx = px - A.x, dy = py - A.y;
        // c0 = q0*dx^2 + q1*dx*dy + q3*dy^2 ; c1 = q2*dx + q4*dy ; c2 = q5
        float t0 = fmaf(B.y, dy, B.x * dx);
        float c0 = fmaf(B.w * dy, dy, dx * t0);
        float c1 = fmaf(C.x, dy, B.z * dx);
        float c2 = C.y;
        float w  = A.w;

        float dz = pz0 - A.z;
        float p  = fmaf(fmaf(c2, dz, c1), dz, c0);
        if (p <= 0.0f) ac0 = fmaf(w, ex2_fast(p), ac0);
        dz += STEP;
        p = fmaf(fmaf(c2, dz, c1), dz, c0);
        if (p <= 0.0f) ac1 = fmaf(w, ex2_fast(p), ac1);
        dz += STEP;
        p = fmaf(fmaf(c2, dz, c1), dz, c0);
        if (p <= 0.0f) ac2 = fmaf(w, ex2_fast(p), ac2);
        dz += STEP;
        p = fmaf(fmaf(c2, dz, c1), dz, c0);
        if (p <= 0.0f) ac3 = fmaf(w, ex2_fast(p), ac3);
    }

    // combine the two splits (h=0,1) sharing a column within each warp
    ac0 += __shfl_xor_sync(0xffffffffu, ac0, 16);
    ac1 += __shfl_xor_sync(0xffffffffu, ac1, 16);
    ac2 += __shfl_xor_sync(0xffffffffu, ac2, 16);
    ac3 += __shfl_xor_sync(0xffffffffu, ac3, 16);

    if (lane < 16)   // lanes 0..15 hold the warp's per-column partials
        *reinterpret_cast<float4*>(&red[wi][col * 4]) = make_float4(ac0, ac1, ac2, ac3);
    __syncthreads();

    if (t < 64) {
        float s = 0.0f;
#pragma unroll
        for (int k = 0; k < 8; k++) s += red[k][t];
        int oi2 = t >> 4, oj2 = (t >> 2) & 3, ok2 = t & 3;
        out[((bi * SS + oi2) * RES + (bj * SS + oj2)) * RES + (bk * SS + ok2)] = s;
    }
}

// ============================================================
extern "C" void kernel_launch(void* const* d_in, const int* in_sizes, int n_in,
                              void* d_out, int out_size) {
    const float* xyz     = (const float*)d_in[0];
    const float* scaling = (const float*)d_in[1];
    const float* rot     = (const float*)d_in[2];
    const float* opac    = (const float*)d_in[3];
    float* out = (float*)d_out;

    kA<<<16, 1024>>>(xyz, scaling, rot, opac);
    kmain<<<NB * NB * NB, 256>>>(out);
}

// round 14
// speedup vs baseline: 1.2692x; 1.2225x over previous
#include <cuda_runtime.h>
#include <math.h>

#define NG     4096
#define NB     16
#define SS     4
#define RES    64
#define RELAX  0.1875f             // (2/16)*1.5
#define STEP   (2.0f/63.0f)
#define LOG2E  1.4426950408889634f
#define NW     (NG/32)             // 128 mask words

__device__ __forceinline__ float ex2_fast(float x) {
    float y;
    asm("ex2.approx.ftz.f32 %0, %1;" : "=f"(y) : "f"(x));
    return y;
}

// ---- scratch ----
__device__ float4   g_par[NG * 3];          // (cx,cy,cz,w) (q0,q1,q2,q3) (q4,q5,_,_)
__device__ unsigned g_mask[3][NB][NW];      // per-axis, per-slot occupancy bitmask

// ============================================================
// Kernel A: 16 CTAs x 1024 thr. Redundant center/scale per CTA
// (front-batched loads), then threads 0..255 prep 256 gaussians
// and warps 0..7 emit mask words.  (unchanged — proven)
// ============================================================
__global__ void __launch_bounds__(1024) kA(const float* __restrict__ xyz,
                                           const float* __restrict__ scaling,
                                           const float* __restrict__ rot,
                                           const float* __restrict__ opac) {
    __shared__ float wmn[32][3], wmx[32][3];
    __shared__ float bc[4];
    const int t = threadIdx.x, lane = t & 31, wi = t >> 5;
    const int b = blockIdx.x;

    float ox[4], vx[4], vy[4], vz[4];
#pragma unroll
    for (int i = 0; i < 4; i++) {
        int g = i * 1024 + t;
        ox[i] = opac[g];
        vx[i] = xyz[3 * g];
        vy[i] = xyz[3 * g + 1];
        vz[i] = xyz[3 * g + 2];
    }
    float mn0 = 1e10f, mn1 = 1e10f, mn2 = 1e10f;
    float mx0 = -1e10f, mx1 = -1e10f, mx2 = -1e10f;
#pragma unroll
    for (int i = 0; i < 4; i++) {
        float s = 1.0f / (1.0f + __expf(-ox[i]));
        if (s > 0.005f) {
            mn0 = fminf(mn0, vx[i]); mn1 = fminf(mn1, vy[i]); mn2 = fminf(mn2, vz[i]);
            mx0 = fmaxf(mx0, vx[i]); mx1 = fmaxf(mx1, vy[i]); mx2 = fmaxf(mx2, vz[i]);
        }
    }
#pragma unroll
    for (int s = 16; s; s >>= 1) {
        mn0 = fminf(mn0, __shfl_xor_sync(0xffffffffu, mn0, s));
        mn1 = fminf(mn1, __shfl_xor_sync(0xffffffffu, mn1, s));
        mn2 = fminf(mn2, __shfl_xor_sync(0xffffffffu, mn2, s));
        mx0 = fmaxf(mx0, __shfl_xor_sync(0xffffffffu, mx0, s));
        mx1 = fmaxf(mx1, __shfl_xor_sync(0xffffffffu, mx1, s));
        mx2 = fmaxf(mx2, __shfl_xor_sync(0xffffffffu, mx2, s));
    }
    if (lane == 0) {
        wmn[wi][0] = mn0; wmn[wi][1] = mn1; wmn[wi][2] = mn2;
        wmx[wi][0] = mx0; wmx[wi][1] = mx1; wmx[wi][2] = mx2;
    }
    __syncthreads();
    if (wi == 0) {
        float a0 = wmn[lane][0], a1 = wmn[lane][1], a2 = wmn[lane][2];
        float b0 = wmx[lane][0], b1 = wmx[lane][1], b2 = wmx[lane][2];
#pragma unroll
        for (int s = 16; s; s >>= 1) {
            a0 = fminf(a0, __shfl_xor_sync(0xffffffffu, a0, s));
            a1 = fminf(a1, __shfl_xor_sync(0xffffffffu, a1, s));
            a2 = fminf(a2, __shfl_xor_sync(0xffffffffu, a2, s));
            b0 = fmaxf(b0, __shfl_xor_sync(0xffffffffu, b0, s));
            b1 = fmaxf(b1, __shfl_xor_sync(0xffffffffu, b1, s));
            b2 = fmaxf(b2, __shfl_xor_sync(0xffffffffu, b2, s));
        }
        if (lane == 0) {
            bc[0] = (a0 + b0) * 0.5f;
            bc[1] = (a1 + b1) * 0.5f;
            bc[2] = (a2 + b2) * 0.5f;
            bc[3] = 1.8f / fmaxf(fmaxf(b0 - a0, b1 - a1), b2 - a2);
        }
    }
    __syncthreads();
    if (t >= 256) return;

    const float cx = bc[0], cy = bc[1], cz = bc[2], sc = bc[3];

    const int g = b * 256 + t;
    float gx = (xyz[3 * g]     - cx) * sc;
    float gy = (xyz[3 * g + 1] - cy) * sc;
    float gz = (xyz[3 * g + 2] - cz) * sc;
    float o  = opac[g];
    float sig = 1.0f / (1.0f + __expf(-o));
    float w  = (sig > 0.005f) ? sig : 0.0f;

    float s0 = __expf(scaling[3 * g])     * sc;
    float s1 = __expf(scaling[3 * g + 1]) * sc;
    float s2 = __expf(scaling[3 * g + 2]) * sc;

    float r = rot[4 * g], x = rot[4 * g + 1], y = rot[4 * g + 2], z = rot[4 * g + 3];
    float rn = 1.0f / sqrtf(r * r + x * x + y * y + z * z);
    r *= rn; x *= rn; y *= rn; z *= rn;

    float R00 = 1.0f - 2.0f * (y * y + z * z);
    float R01 = 2.0f * (x * y - r * z);
    float R02 = 2.0f * (x * z + r * y);
    float R10 = 2.0f * (x * y + r * z);
    float R11 = 1.0f - 2.0f * (x * x + z * z);
    float R12 = 2.0f * (y * z - r * x);
    float R20 = 2.0f * (x * z - r * y);
    float R21 = 2.0f * (y * z + r * x);
    float R22 = 1.0f - 2.0f * (x * x + y * y);

    float L00 = R00 * s0, L01 = R01 * s1, L02 = R02 * s2;
    float L10 = R10 * s0, L11 = R11 * s1, L12 = R12 * s2;
    float L20 = R20 * s0, L21 = R21 * s1, L22 = R22 * s2;

    float a  = L00 * L00 + L01 * L01 + L02 * L02;
    float bb = L00 * L10 + L01 * L11 + L02 * L12;
    float c  = L00 * L20 + L01 * L21 + L02 * L22;
    float d  = L10 * L10 + L11 * L11 + L12 * L12;
    float e  = L10 * L20 + L11 * L21 + L12 * L22;
    float f  = L20 * L20 + L21 * L21 + L22 * L22;

    float det = a * d * f + 2.0f * e * c * bb - e * e * a - c * c * d - bb * bb * f + 1e-24f;
    float id  = 1.0f / det;
    float q0 = (d * f - e * e)   * id * (-0.5f * LOG2E);
    float q1 = (e * c - bb * f)  * id * (-LOG2E);
    float q2 = (e * bb - c * d)  * id * (-LOG2E);
    float q3 = (a * f - c * c)   * id * (-0.5f * LOG2E);
    float q4 = (bb * c - e * a)  * id * (-LOG2E);
    float q5 = (a * d - bb * bb) * id * (-0.5f * LOG2E);

    g_par[3 * g]     = make_float4(gx, gy, gz, w);
    g_par[3 * g + 1] = make_float4(q0, q1, q2, q3);
    g_par[3 * g + 2] = make_float4(q4, q5, 0.0f, 0.0f);

    const int word = b * 8 + wi;
#pragma unroll 1
    for (int s = 0; s < 16; s++) {
        float lo = -1.0f + STEP * (float)(s * SS)          - RELAX;
        float hi = -1.0f + STEP * (float)(s * SS + SS - 1) + RELAX;
        unsigned bx = __ballot_sync(0xffffffffu, (w > 0.0f) && (gx > lo) && (gx < hi));
        unsigned by = __ballot_sync(0xffffffffu, (gy > lo) && (gy < hi));
        unsigned bz = __ballot_sync(0xffffffffu, (gz > lo) && (gz < hi));
        if (lane == 0) {
            g_mask[0][s][word] = bx;
            g_mask[1][s][word] = by;
            g_mask[2][s][word] = bz;
        }
    }
}

// ============================================================
// Kernel B: one CTA per 4x4x4 block, 256 threads — EXACT round-11
// form (best measured: 25.9us), plus PDL grid-dependency sync so
// the prologue overlaps kA's tail.
// ============================================================
__global__ void __launch_bounds__(256, 8) kmain(float* __restrict__ out) {
    __shared__ unsigned short list[NG];   // 8 KB, holds 3*g
    __shared__ float red[8][64];          // 2 KB  [warp][point]
    __shared__ int   wtot[4];

    const int b  = (blockIdx.x * 1357) & 4095;   // bijective scramble
    const int bi = b >> 8, bj = (b >> 4) & 15, bk = b & 15;
    const int t  = threadIdx.x, lane = t & 31, wi = t >> 5;

    // wait for kA's writes to be visible (PDL)
    cudaGridDependencySynchronize();

    // ---- mask AND + deterministic compaction (threads 0..127) ----
    unsigned m = 0; int lc = 0; int inc = 0;
    if (t < NW) {
        m  = g_mask[0][bi][t] & g_mask[1][bj][t] & g_mask[2][bk][t];
        lc = __popc(m);
        inc = lc;
#pragma unroll
        for (int s = 1; s < 32; s <<= 1) {
            int v = __shfl_up_sync(0xffffffffu, inc, s);
            if (lane >= s) inc += v;
        }
        if (lane == 31) wtot[wi] = inc;
    }
    __syncthreads();
    const int cnt = wtot[0] + wtot[1] + wtot[2] + wtot[3];   // all threads
    if (t < NW) {
        int base = 0;
#pragma unroll
        for (int k = 0; k < 3; k++) if (wi > k) base += wtot[k];
        int off = base + inc - lc;
        unsigned gb = (unsigned)t * 32u;
        unsigned mm = m;
        while (mm) {
            int bp = __ffs(mm) - 1;
            mm &= mm - 1;
            list[off++] = (unsigned short)(3u * (gb + bp));
        }
    }
    __syncthreads();

    if (cnt == 0) {
        if (t < 64) {
            int oi = t >> 4, oj = (t >> 2) & 3, ok = t & 3;
            out[((bi * SS + oi) * RES + (bj * SS + oj)) * RES + (bk * SS + ok)] = 0.0f;
        }
        return;
    }

    // thread role: column (x,y) + split id
    const int col = lane & 15;             // 0..15
    const int h   = lane >> 4;             // half-warp
    const int sid = wi * 2 + h;            // split 0..15
    const int oi  = col >> 2, oj = col & 3;

    const float px  = -1.0f + STEP * (float)(bi * SS + oi);
    const float py  = -1.0f + STEP * (float)(bj * SS + oj);
    const float pz0 = -1.0f + STEP * (float)(bk * SS);

    const float4* __restrict__ par = g_par;

    float ac0 = 0.0f, ac1 = 0.0f, ac2 = 0.0f, ac3 = 0.0f;

#pragma unroll 2
    for (int j = sid; j < cnt; j += 16) {
        int g3 = list[j];
        float4 A = par[g3];
        float4 B = par[g3 + 1];
        float4 C = par[g3 + 2];
        float dx = px - A.x, dy = py - A.y;
        // c0 = q0*dx^2 + q1*dx*dy + q3*dy^2 ; c1 = q2*dx + q4*dy ; c2 = q5
        float t0 = fmaf(B.y, dy, B.x * dx);
        float c0 = fmaf(B.w * dy, dy, dx * t0);
        float c1 = fmaf(C.x, dy, B.z * dx);
        float c2 = C.y;
        float w  = A.w;

        float dz = pz0 - A.z;
        float p  = fmaf(fmaf(c2, dz, c1), dz, c0);
        if (p <= 0.0f) ac0 = fmaf(w, ex2_fast(p), ac0);
        dz += STEP;
        p = fmaf(fmaf(c2, dz, c1), dz, c0);
        if (p <= 0.0f) ac1 = fmaf(w, ex2_fast(p), ac1);
        dz += STEP;
        p = fmaf(fmaf(c2, dz, c1), dz, c0);
        if (p <= 0.0f) ac2 = fmaf(w, ex2_fast(p), ac2);
        dz += STEP;
        p = fmaf(fmaf(c2, dz, c1), dz, c0);
        if (p <= 0.0f) ac3 = fmaf(w, ex2_fast(p), ac3);
    }

    // combine the two splits (h=0,1) sharing a column within each warp
    ac0 += __shfl_xor_sync(0xffffffffu, ac0, 16);
    ac1 += __shfl_xor_sync(0xffffffffu, ac1, 16);
    ac2 += __shfl_xor_sync(0xffffffffu, ac2, 16);
    ac3 += __shfl_xor_sync(0xffffffffu, ac3, 16);

    if (lane < 16)   // lanes 0..15 hold the warp's per-column partials
        *reinterpret_cast<float4*>(&red[wi][col * 4]) = make_float4(ac0, ac1, ac2, ac3);
    __syncthreads();

    if (t < 64) {
        float s = 0.0f;
#pragma unroll
        for (int k = 0; k < 8; k++) s += red[k][t];
        int oi2 = t >> 4, oj2 = (t >> 2) & 3, ok2 = t & 3;
        out[((bi * SS + oi2) * RES + (bj * SS + oj2)) * RES + (bk * SS + ok2)] = s;
    }
}

// ============================================================
extern "C" void kernel_launch(void* const* d_in, const int* in_sizes, int n_in,
                              void* d_out, int out_size) {
    const float* xyz     = (const float*)d_in[0];
    const float* scaling = (const float*)d_in[1];
    const float* rot     = (const float*)d_in[2];
    const float* opac    = (const float*)d_in[3];
    float* out = (float*)d_out;

    kA<<<16, 1024>>>(xyz, scaling, rot, opac);

    // PDL: let kmain's prologue overlap kA's tail
    cudaLaunchConfig_t cfg = {};
    cfg.gridDim  = dim3(NB * NB * NB, 1, 1);
    cfg.blockDim = dim3(256, 1, 1);
    cudaLaunchAttribute attrs[1];
    attrs[0].id = cudaLaunchAttributeProgrammaticStreamSerialization;
    attrs[0].val.programmaticStreamSerializationAllowed = 1;
    cfg.attrs = attrs;
    cfg.numAttrs = 1;
    cudaLaunchKernelEx(&cfg, kmain, out);
}

// round 15
// speedup vs baseline: 1.4518x; 1.1439x over previous
#include <cuda_runtime.h>
#include <math.h>

#define NG     4096
#define NB     16
#define SS     4
#define RES    64
#define RELAX  0.1875f             // (2/16)*1.5
#define STEP   (2.0f/63.0f)
#define LOG2E  1.4426950408889634f
#define NW     (NG/32)             // 128 mask words

__device__ __forceinline__ float ex2_fast(float x) {
    float y;
    asm("ex2.approx.ftz.f32 %0, %1;" : "=f"(y) : "f"(x));
    return y;
}

// center-out axis order: 0->8, 1->7, 2->9, 3->6, ... 15->0
__device__ __forceinline__ int cout16(int i) {
    int off = (i + 1) >> 1;
    return (i & 1) ? (8 - off) : (8 + off);
}

// ---- scratch ----
__device__ float4   g_par[NG * 3];          // (cx,cy,cz,w) (q0,q1,q2,q3) (q4,q5,_,_)
__device__ unsigned g_mask[3][NB][NW];      // per-axis, per-slot occupancy bitmask

// ============================================================
// Kernel A: 16 CTAs x 1024 thr. Redundant center/scale per CTA
// (front-batched loads), then threads 0..255 prep 256 gaussians
// and warps 0..7 emit mask words. Ballot loop now unrolled (ILP).
// ============================================================
__global__ void __launch_bounds__(1024) kA(const float* __restrict__ xyz,
                                           const float* __restrict__ scaling,
                                           const float* __restrict__ rot,
                                           const float* __restrict__ opac) {
    __shared__ float wmn[32][3], wmx[32][3];
    __shared__ float bc[4];
    const int t = threadIdx.x, lane = t & 31, wi = t >> 5;
    const int b = blockIdx.x;

    float ox[4], vx[4], vy[4], vz[4];
#pragma unroll
    for (int i = 0; i < 4; i++) {
        int g = i * 1024 + t;
        ox[i] = opac[g];
        vx[i] = xyz[3 * g];
        vy[i] = xyz[3 * g + 1];
        vz[i] = xyz[3 * g + 2];
    }
    float mn0 = 1e10f, mn1 = 1e10f, mn2 = 1e10f;
    float mx0 = -1e10f, mx1 = -1e10f, mx2 = -1e10f;
#pragma unroll
    for (int i = 0; i < 4; i++) {
        float s = 1.0f / (1.0f + __expf(-ox[i]));
        if (s > 0.005f) {
            mn0 = fminf(mn0, vx[i]); mn1 = fminf(mn1, vy[i]); mn2 = fminf(mn2, vz[i]);
            mx0 = fmaxf(mx0, vx[i]); mx1 = fmaxf(mx1, vy[i]); mx2 = fmaxf(mx2, vz[i]);
        }
    }
#pragma unroll
    for (int s = 16; s; s >>= 1) {
        mn0 = fminf(mn0, __shfl_xor_sync(0xffffffffu, mn0, s));
        mn1 = fminf(mn1, __shfl_xor_sync(0xffffffffu, mn1, s));
        mn2 = fminf(mn2, __shfl_xor_sync(0xffffffffu, mn2, s));
        mx0 = fmaxf(mx0, __shfl_xor_sync(0xffffffffu, mx0, s));
        mx1 = fmaxf(mx1, __shfl_xor_sync(0xffffffffu, mx1, s));
        mx2 = fmaxf(mx2, __shfl_xor_sync(0xffffffffu, mx2, s));
    }
    if (lane == 0) {
        wmn[wi][0] = mn0; wmn[wi][1] = mn1; wmn[wi][2] = mn2;
        wmx[wi][0] = mx0; wmx[wi][1] = mx1; wmx[wi][2] = mx2;
    }
    __syncthreads();
    if (wi == 0) {
        float a0 = wmn[lane][0], a1 = wmn[lane][1], a2 = wmn[lane][2];
        float b0 = wmx[lane][0], b1 = wmx[lane][1], b2 = wmx[lane][2];
#pragma unroll
        for (int s = 16; s; s >>= 1) {
            a0 = fminf(a0, __shfl_xor_sync(0xffffffffu, a0, s));
            a1 = fminf(a1, __shfl_xor_sync(0xffffffffu, a1, s));
            a2 = fminf(a2, __shfl_xor_sync(0xffffffffu, a2, s));
            b0 = fmaxf(b0, __shfl_xor_sync(0xffffffffu, b0, s));
            b1 = fmaxf(b1, __shfl_xor_sync(0xffffffffu, b1, s));
            b2 = fmaxf(b2, __shfl_xor_sync(0xffffffffu, b2, s));
        }
        if (lane == 0) {
            bc[0] = (a0 + b0) * 0.5f;
            bc[1] = (a1 + b1) * 0.5f;
            bc[2] = (a2 + b2) * 0.5f;
            bc[3] = 1.8f / fmaxf(fmaxf(b0 - a0, b1 - a1), b2 - a2);
        }
    }
    __syncthreads();
    if (t >= 256) return;

    const float cx = bc[0], cy = bc[1], cz = bc[2], sc = bc[3];

    const int g = b * 256 + t;
    float gx = (xyz[3 * g]     - cx) * sc;
    float gy = (xyz[3 * g + 1] - cy) * sc;
    float gz = (xyz[3 * g + 2] - cz) * sc;
    float o  = opac[g];
    float sig = 1.0f / (1.0f + __expf(-o));
    float w  = (sig > 0.005f) ? sig : 0.0f;

    float s0 = __expf(scaling[3 * g])     * sc;
    float s1 = __expf(scaling[3 * g + 1]) * sc;
    float s2 = __expf(scaling[3 * g + 2]) * sc;

    float r = rot[4 * g], x = rot[4 * g + 1], y = rot[4 * g + 2], z = rot[4 * g + 3];
    float rn = 1.0f / sqrtf(r * r + x * x + y * y + z * z);
    r *= rn; x *= rn; y *= rn; z *= rn;

    float R00 = 1.0f - 2.0f * (y * y + z * z);
    float R01 = 2.0f * (x * y - r * z);
    float R02 = 2.0f * (x * z + r * y);
    float R10 = 2.0f * (x * y + r * z);
    float R11 = 1.0f - 2.0f * (x * x + z * z);
    float R12 = 2.0f * (y * z - r * x);
    float R20 = 2.0f * (x * z - r * y);
    float R21 = 2.0f * (y * z + r * x);
    float R22 = 1.0f - 2.0f * (x * x + y * y);

    float L00 = R00 * s0, L01 = R01 * s1, L02 = R02 * s2;
    float L10 = R10 * s0, L11 = R11 * s1, L12 = R12 * s2;
    float L20 = R20 * s0, L21 = R21 * s1, L22 = R22 * s2;

    float a  = L00 * L00 + L01 * L01 + L02 * L02;
    float bb = L00 * L10 + L01 * L11 + L02 * L12;
    float c  = L00 * L20 + L01 * L21 + L02 * L22;
    float d  = L10 * L10 + L11 * L11 + L12 * L12;
    float e  = L10 * L20 + L11 * L21 + L12 * L22;
    float f  = L20 * L20 + L21 * L21 + L22 * L22;

    float det = a * d * f + 2.0f * e * c * bb - e * e * a - c * c * d - bb * bb * f + 1e-24f;
    float id  = 1.0f / det;
    float q0 = (d * f - e * e)   * id * (-0.5f * LOG2E);
    float q1 = (e * c - bb * f)  * id * (-LOG2E);
    float q2 = (e * bb - c * d)  * id * (-LOG2E);
    float q3 = (a * f - c * c)   * id * (-0.5f * LOG2E);
    float q4 = (bb * c - e * a)  * id * (-LOG2E);
    float q5 = (a * d - bb * bb) * id * (-0.5f * LOG2E);

    g_par[3 * g]     = make_float4(gx, gy, gz, w);
    g_par[3 * g + 1] = make_float4(q0, q1, q2, q3);
    g_par[3 * g + 2] = make_float4(q4, q5, 0.0f, 0.0f);

    const int word = b * 8 + wi;
#pragma unroll
    for (int s = 0; s < 16; s++) {
        float lo = -1.0f + STEP * (float)(s * SS)          - RELAX;
        float hi = -1.0f + STEP * (float)(s * SS + SS - 1) + RELAX;
        unsigned bx = __ballot_sync(0xffffffffu, (w > 0.0f) && (gx > lo) && (gx < hi));
        unsigned by = __ballot_sync(0xffffffffu, (gy > lo) && (gy < hi));
        unsigned bz = __ballot_sync(0xffffffffu, (gz > lo) && (gz < hi));
        if (lane == 0) {
            g_mask[0][s][word] = bx;
            g_mask[1][s][word] = by;
            g_mask[2][s][word] = bz;
        }
    }
}

// ============================================================
// Kernel B: one CTA per 4x4x4 block, 256 threads — round-11 body.
// Block ids mapped CENTER-OUT so heavy central blocks launch
// first (LPT scheduling): the end-game tail is boundary blocks.
// ============================================================
__global__ void __launch_bounds__(256, 8) kmain(float* __restrict__ out) {
    __shared__ unsigned short list[NG];   // 8 KB, holds 3*g
    __shared__ float red[8][64];          // 2 KB  [warp][point]
    __shared__ int   wtot[4];

    const int q  = blockIdx.x;
    const int bi = cout16(q >> 8);
    const int bj = cout16((q >> 4) & 15);
    const int bk = cout16(q & 15);
    const int t  = threadIdx.x, lane = t & 31, wi = t >> 5;

    // wait for kA's writes to be visible (PDL)
    cudaGridDependencySynchronize();

    // ---- mask AND + deterministic compaction (threads 0..127) ----
    unsigned m = 0; int lc = 0; int inc = 0;
    if (t < NW) {
        m  = g_mask[0][bi][t] & g_mask[1][bj][t] & g_mask[2][bk][t];
        lc = __popc(m);
        inc = lc;
#pragma unroll
        for (int s = 1; s < 32; s <<= 1) {
            int v = __shfl_up_sync(0xffffffffu, inc, s);
            if (lane >= s) inc += v;
        }
        if (lane == 31) wtot[wi] = inc;
    }
    __syncthreads();
    const int cnt = wtot[0] + wtot[1] + wtot[2] + wtot[3];   // all threads
    if (t < NW) {
        int base = 0;
#pragma unroll
        for (int k = 0; k < 3; k++) if (wi > k) base += wtot[k];
        int off = base + inc - lc;
        unsigned gb = (unsigned)t * 32u;
        unsigned mm = m;
        while (mm) {
            int bp = __ffs(mm) - 1;
            mm &= mm - 1;
            list[off++] = (unsigned short)(3u * (gb + bp));
        }
    }
    __syncthreads();

    if (cnt == 0) {
        if (t < 64) {
            int oi = t >> 4, oj = (t >> 2) & 3, ok = t & 3;
            out[((bi * SS + oi) * RES + (bj * SS + oj)) * RES + (bk * SS + ok)] = 0.0f;
        }
        return;
    }

    // thread role: column (x,y) + split id
    const int col = lane & 15;             // 0..15
    const int h   = lane >> 4;             // half-warp
    const int sid = wi * 2 + h;            // split 0..15
    const int oi  = col >> 2, oj = col & 3;

    const float px  = -1.0f + STEP * (float)(bi * SS + oi);
    const float py  = -1.0f + STEP * (float)(bj * SS + oj);
    const float pz0 = -1.0f + STEP * (float)(bk * SS);

    const float4* __restrict__ par = g_par;

    float ac0 = 0.0f, ac1 = 0.0f, ac2 = 0.0f, ac3 = 0.0f;

#pragma unroll 2
    for (int j = sid; j < cnt; j += 16) {
        int g3 = list[j];
        float4 A = par[g3];
        float4 B = par[g3 + 1];
        float4 C = par[g3 + 2];
        float dx = px - A.x, dy = py - A.y;
        // c0 = q0*dx^2 + q1*dx*dy + q3*dy^2 ; c1 = q2*dx + q4*dy ; c2 = q5
        float t0 = fmaf(B.y, dy, B.x * dx);
        float c0 = fmaf(B.w * dy, dy, dx * t0);
        float c1 = fmaf(C.x, dy, B.z * dx);
        float c2 = C.y;
        float w  = A.w;

        float dz = pz0 - A.z;
        float p  = fmaf(fmaf(c2, dz, c1), dz, c0);
        if (p <= 0.0f) ac0 = fmaf(w, ex2_fast(p), ac0);
        dz += STEP;
        p = fmaf(fmaf(c2, dz, c1), dz, c0);
        if (p <= 0.0f) ac1 = fmaf(w, ex2_fast(p), ac1);
        dz += STEP;
        p = fmaf(fmaf(c2, dz, c1), dz, c0);
        if (p <= 0.0f) ac2 = fmaf(w, ex2_fast(p), ac2);
        dz += STEP;
        p = fmaf(fmaf(c2, dz, c1), dz, c0);
        if (p <= 0.0f) ac3 = fmaf(w, ex2_fast(p), ac3);
    }

    // combine the two splits (h=0,1) sharing a column within each warp
    ac0 += __shfl_xor_sync(0xffffffffu, ac0, 16);
    ac1 += __shfl_xor_sync(0xffffffffu, ac1, 16);
    ac2 += __shfl_xor_sync(0xffffffffu, ac2, 16);
    ac3 += __shfl_xor_sync(0xffffffffu, ac3, 16);

    if (lane < 16)   // lanes 0..15 hold the warp's per-column partials
        *reinterpret_cast<float4*>(&red[wi][col * 4]) = make_float4(ac0, ac1, ac2, ac3);
    __syncthreads();

    if (t < 64) {
        float s = 0.0f;
#pragma unroll
        for (int k = 0; k < 8; k++) s += red[k][t];
        int oi2 = t >> 4, oj2 = (t >> 2) & 3, ok2 = t & 3;
        out[((bi * SS + oi2) * RES + (bj * SS + oj2)) * RES + (bk * SS + ok2)] = s;
    }
}

// ============================================================
extern "C" void kernel_launch(void* const* d_in, const int* in_sizes, int n_in,
                              void* d_out, int out_size) {
    const float* xyz     = (const float*)d_in[0];
    const float* scaling = (const float*)d_in[1];
    const float* rot     = (const float*)d_in[2];
    const float* opac    = (const float*)d_in[3];
    float* out = (float*)d_out;

    kA<<<16, 1024>>>(xyz, scaling, rot, opac);

    // PDL: let kmain's prologue overlap kA's tail
    cudaLaunchConfig_t cfg = {};
    cfg.gridDim  = dim3(NB * NB * NB, 1, 1);
    cfg.blockDim = dim3(256, 1, 1);
    cudaLaunchAttribute attrs[1];
    attrs[0].id = cudaLaunchAttributeProgrammaticStreamSerialization;
    attrs[0].val.programmaticStreamSerializationAllowed = 1;
    cfg.attrs = attrs;
    cfg.numAttrs = 1;
    cudaLaunchKernelEx(&cfg, kmain, out);
}

// round 16
// speedup vs baseline: 1.5417x; 1.0619x over previous
#include <cuda_runtime.h>
#include <math.h>

#define NG     4096
#define NB     16
#define SS     4
#define RES    64
#define RELAX  0.1875f             // (2/16)*1.5
#define STEP   (2.0f/63.0f)
#define LOG2E  1.4426950408889634f
#define NW     (NG/32)             // 128 mask words

__device__ __forceinline__ float ex2_fast(float x) {
    float y;
    asm("ex2.approx.ftz.f32 %0, %1;" : "=f"(y) : "f"(x));
    return y;
}

// center-out axis order: 0->8, 1->7, 2->9, 3->6, ... 15->0
__device__ __forceinline__ int cout16(int i) {
    int off = (i + 1) >> 1;
    return (i & 1) ? (8 - off) : (8 + off);
}

// ---- scratch ----
__device__ float4   g_par[NG * 3];          // (cx,cy,cz,w) (q0,q1,q2,q3) (q4,q5,_,_)
__device__ unsigned g_mask[3][NB][NW];      // per-axis, per-slot occupancy bitmask

// ============================================================
// Kernel A: 16 CTAs x 1024 thr. Redundant center/scale per CTA
// (front-batched loads), then threads 0..255 prep 256 gaussians
// and warps 0..7 emit mask words.  (proven — unchanged)
// ============================================================
__global__ void __launch_bounds__(1024) kA(const float* __restrict__ xyz,
                                           const float* __restrict__ scaling,
                                           const float* __restrict__ rot,
                                           const float* __restrict__ opac) {
    __shared__ float wmn[32][3], wmx[32][3];
    __shared__ float bc[4];
    const int t = threadIdx.x, lane = t & 31, wi = t >> 5;
    const int b = blockIdx.x;

    float ox[4], vx[4], vy[4], vz[4];
#pragma unroll
    for (int i = 0; i < 4; i++) {
        int g = i * 1024 + t;
        ox[i] = opac[g];
        vx[i] = xyz[3 * g];
        vy[i] = xyz[3 * g + 1];
        vz[i] = xyz[3 * g + 2];
    }
    float mn0 = 1e10f, mn1 = 1e10f, mn2 = 1e10f;
    float mx0 = -1e10f, mx1 = -1e10f, mx2 = -1e10f;
#pragma unroll
    for (int i = 0; i < 4; i++) {
        float s = 1.0f / (1.0f + __expf(-ox[i]));
        if (s > 0.005f) {
            mn0 = fminf(mn0, vx[i]); mn1 = fminf(mn1, vy[i]); mn2 = fminf(mn2, vz[i]);
            mx0 = fmaxf(mx0, vx[i]); mx1 = fmaxf(mx1, vy[i]); mx2 = fmaxf(mx2, vz[i]);
        }
    }
#pragma unroll
    for (int s = 16; s; s >>= 1) {
        mn0 = fminf(mn0, __shfl_xor_sync(0xffffffffu, mn0, s));
        mn1 = fminf(mn1, __shfl_xor_sync(0xffffffffu, mn1, s));
        mn2 = fminf(mn2, __shfl_xor_sync(0xffffffffu, mn2, s));
        mx0 = fmaxf(mx0, __shfl_xor_sync(0xffffffffu, mx0, s));
        mx1 = fmaxf(mx1, __shfl_xor_sync(0xffffffffu, mx1, s));
        mx2 = fmaxf(mx2, __shfl_xor_sync(0xffffffffu, mx2, s));
    }
    if (lane == 0) {
        wmn[wi][0] = mn0; wmn[wi][1] = mn1; wmn[wi][2] = mn2;
        wmx[wi][0] = mx0; wmx[wi][1] = mx1; wmx[wi][2] = mx2;
    }
    __syncthreads();
    if (wi == 0) {
        float a0 = wmn[lane][0], a1 = wmn[lane][1], a2 = wmn[lane][2];
        float b0 = wmx[lane][0], b1 = wmx[lane][1], b2 = wmx[lane][2];
#pragma unroll
        for (int s = 16; s; s >>= 1) {
            a0 = fminf(a0, __shfl_xor_sync(0xffffffffu, a0, s));
            a1 = fminf(a1, __shfl_xor_sync(0xffffffffu, a1, s));
            a2 = fminf(a2, __shfl_xor_sync(0xffffffffu, a2, s));
            b0 = fmaxf(b0, __shfl_xor_sync(0xffffffffu, b0, s));
            b1 = fmaxf(b1, __shfl_xor_sync(0xffffffffu, b1, s));
            b2 = fmaxf(b2, __shfl_xor_sync(0xffffffffu, b2, s));
        }
        if (lane == 0) {
            bc[0] = (a0 + b0) * 0.5f;
            bc[1] = (a1 + b1) * 0.5f;
            bc[2] = (a2 + b2) * 0.5f;
            bc[3] = 1.8f / fmaxf(fmaxf(b0 - a0, b1 - a1), b2 - a2);
        }
    }
    __syncthreads();
    if (t >= 256) return;

    const float cx = bc[0], cy = bc[1], cz = bc[2], sc = bc[3];

    const int g = b * 256 + t;
    float gx = (xyz[3 * g]     - cx) * sc;
    float gy = (xyz[3 * g + 1] - cy) * sc;
    float gz = (xyz[3 * g + 2] - cz) * sc;
    float o  = opac[g];
    float sig = 1.0f / (1.0f + __expf(-o));
    float w  = (sig > 0.005f) ? sig : 0.0f;

    float s0 = __expf(scaling[3 * g])     * sc;
    float s1 = __expf(scaling[3 * g + 1]) * sc;
    float s2 = __expf(scaling[3 * g + 2]) * sc;

    float r = rot[4 * g], x = rot[4 * g + 1], y = rot[4 * g + 2], z = rot[4 * g + 3];
    float rn = 1.0f / sqrtf(r * r + x * x + y * y + z * z);
    r *= rn; x *= rn; y *= rn; z *= rn;

    float R00 = 1.0f - 2.0f * (y * y + z * z);
    float R01 = 2.0f * (x * y - r * z);
    float R02 = 2.0f * (x * z + r * y);
    float R10 = 2.0f * (x * y + r * z);
    float R11 = 1.0f - 2.0f * (x * x + z * z);
    float R12 = 2.0f * (y * z - r * x);
    float R20 = 2.0f * (x * z - r * y);
    float R21 = 2.0f * (y * z + r * x);
    float R22 = 1.0f - 2.0f * (x * x + y * y);

    float L00 = R00 * s0, L01 = R01 * s1, L02 = R02 * s2;
    float L10 = R10 * s0, L11 = R11 * s1, L12 = R12 * s2;
    float L20 = R20 * s0, L21 = R21 * s1, L22 = R22 * s2;

    float a  = L00 * L00 + L01 * L01 + L02 * L02;
    float bb = L00 * L10 + L01 * L11 + L02 * L12;
    float c  = L00 * L20 + L01 * L21 + L02 * L22;
    float d  = L10 * L10 + L11 * L11 + L12 * L12;
    float e  = L10 * L20 + L11 * L21 + L12 * L22;
    float f  = L20 * L20 + L21 * L21 + L22 * L22;

    float det = a * d * f + 2.0f * e * c * bb - e * e * a - c * c * d - bb * bb * f + 1e-24f;
    float id  = 1.0f / det;
    float q0 = (d * f - e * e)   * id * (-0.5f * LOG2E);
    float q1 = (e * c - bb * f)  * id * (-LOG2E);
    float q2 = (e * bb - c * d)  * id * (-LOG2E);
    float q3 = (a * f - c * c)   * id * (-0.5f * LOG2E);
    float q4 = (bb * c - e * a)  * id * (-LOG2E);
    float q5 = (a * d - bb * bb) * id * (-0.5f * LOG2E);

    g_par[3 * g]     = make_float4(gx, gy, gz, w);
    g_par[3 * g + 1] = make_float4(q0, q1, q2, q3);
    g_par[3 * g + 2] = make_float4(q4, q5, 0.0f, 0.0f);

    const int word = b * 8 + wi;
#pragma unroll
    for (int s = 0; s < 16; s++) {
        float lo = -1.0f + STEP * (float)(s * SS)          - RELAX;
        float hi = -1.0f + STEP * (float)(s * SS + SS - 1) + RELAX;
        unsigned bx = __ballot_sync(0xffffffffu, (w > 0.0f) && (gx > lo) && (gx < hi));
        unsigned by = __ballot_sync(0xffffffffu, (gy > lo) && (gy < hi));
        unsigned bz = __ballot_sync(0xffffffffu, (gz > lo) && (gz < hi));
        if (lane == 0) {
            g_mask[0][s][word] = bx;
            g_mask[1][s][word] = by;
            g_mask[2][s][word] = bz;
        }
    }
}

// ============================================================
// Kernel B: one CTA per 4x4x4 block, 256 threads, center-out LPT.
// Prologue hoisted above the PDL sync (overlaps kA's tail).
// Eval loop unroll 4 with regs unconstrained (ILP over the
// LDS->LDG chain); 16 xy-cols x 16 splits, incremental-dz quad.
// ============================================================
__global__ void __launch_bounds__(256) kmain(float* __restrict__ out) {
    __shared__ unsigned short list[NG];   // 8 KB, holds 3*g
    __shared__ float red[8][64];          // 2 KB  [warp][point]
    __shared__ int   wtot[4];

    // ---- kA-independent prologue (overlaps kA under PDL) ----
    const int q  = blockIdx.x;
    const int bi = cout16(q >> 8);
    const int bj = cout16((q >> 4) & 15);
    const int bk = cout16(q & 15);
    const int t  = threadIdx.x, lane = t & 31, wi = t >> 5;

    const int col = lane & 15;             // 0..15
    const int h   = lane >> 4;             // half-warp
    const int sid = wi * 2 + h;            // split 0..15
    const int oi  = col >> 2, oj = col & 3;

    const float px  = -1.0f + STEP * (float)(bi * SS + oi);
    const float py  = -1.0f + STEP * (float)(bj * SS + oj);
    const float pz0 = -1.0f + STEP * (float)(bk * SS);

    // wait for kA's writes to be visible (PDL)
    cudaGridDependencySynchronize();

    // ---- mask AND + deterministic compaction (threads 0..127) ----
    unsigned m = 0; int lc = 0; int inc = 0;
    if (t < NW) {
        m  = g_mask[0][bi][t] & g_mask[1][bj][t] & g_mask[2][bk][t];
        lc = __popc(m);
        inc = lc;
#pragma unroll
        for (int s = 1; s < 32; s <<= 1) {
            int v = __shfl_up_sync(0xffffffffu, inc, s);
            if (lane >= s) inc += v;
        }
        if (lane == 31) wtot[wi] = inc;
    }
    __syncthreads();
    const int cnt = wtot[0] + wtot[1] + wtot[2] + wtot[3];   // all threads
    if (t < NW) {
        int base = 0;
#pragma unroll
        for (int k = 0; k < 3; k++) if (wi > k) base += wtot[k];
        int off = base + inc - lc;
        unsigned gb = (unsigned)t * 32u;
        unsigned mm = m;
        while (mm) {
            int bp = __ffs(mm) - 1;
            mm &= mm - 1;
            list[off++] = (unsigned short)(3u * (gb + bp));
        }
    }
    __syncthreads();

    if (cnt == 0) {
        if (t < 64) {
            int oi0 = t >> 4, oj0 = (t >> 2) & 3, ok0 = t & 3;
            out[((bi * SS + oi0) * RES + (bj * SS + oj0)) * RES + (bk * SS + ok0)] = 0.0f;
        }
        return;
    }

    const float4* __restrict__ par = g_par;

    float ac0 = 0.0f, ac1 = 0.0f, ac2 = 0.0f, ac3 = 0.0f;

#pragma unroll 4
    for (int j = sid; j < cnt; j += 16) {
        int g3 = list[j];
        float4 A = par[g3];
        float4 B = par[g3 + 1];
        float4 C = par[g3 + 2];
        float dx = px - A.x, dy = py - A.y;
        // c0 = q0*dx^2 + q1*dx*dy + q3*dy^2 ; c1 = q2*dx + q4*dy ; c2 = q5
        float t0 = fmaf(B.y, dy, B.x * dx);
        float c0 = fmaf(B.w * dy, dy, dx * t0);
        float c1 = fmaf(C.x, dy, B.z * dx);
        float c2 = C.y;
        float w  = A.w;

        float dz = pz0 - A.z;
        float p  = fmaf(fmaf(c2, dz, c1), dz, c0);
        if (p <= 0.0f) ac0 = fmaf(w, ex2_fast(p), ac0);
        dz += STEP;
        p = fmaf(fmaf(c2, dz, c1), dz, c0);
        if (p <= 0.0f) ac1 = fmaf(w, ex2_fast(p), ac1);
        dz += STEP;
        p = fmaf(fmaf(c2, dz, c1), dz, c0);
        if (p <= 0.0f) ac2 = fmaf(w, ex2_fast(p), ac2);
        dz += STEP;
        p = fmaf(fmaf(c2, dz, c1), dz, c0);
        if (p <= 0.0f) ac3 = fmaf(w, ex2_fast(p), ac3);
    }

    // combine the two splits (h=0,1) sharing a column within each warp
    ac0 += __shfl_xor_sync(0xffffffffu, ac0, 16);
    ac1 += __shfl_xor_sync(0xffffffffu, ac1, 16);
    ac2 += __shfl_xor_sync(0xffffffffu, ac2, 16);
    ac3 += __shfl_xor_sync(0xffffffffu, ac3, 16);

    if (lane < 16)   // lanes 0..15 hold the warp's per-column partials
        *reinterpret_cast<float4*>(&red[wi][col * 4]) = make_float4(ac0, ac1, ac2, ac3);
    __syncthreads();

    if (t < 64) {
        float s = 0.0f;
#pragma unroll
        for (int k = 0; k < 8; k++) s += red[k][t];
        int oi2 = t >> 4, oj2 = (t >> 2) & 3, ok2 = t & 3;
        out[((bi * SS + oi2) * RES + (bj * SS + oj2)) * RES + (bk * SS + ok2)] = s;
    }
}

// ============================================================
extern "C" void kernel_launch(void* const* d_in, const int* in_sizes, int n_in,
                              void* d_out, int out_size) {
    const float* xyz     = (const float*)d_in[0];
    const float* scaling = (const float*)d_in[1];
    const float* rot     = (const float*)d_in[2];
    const float* opac    = (const float*)d_in[3];
    float* out = (float*)d_out;

    kA<<<16, 1024>>>(xyz, scaling, rot, opac);

    // PDL: let kmain's prologue overlap kA's tail
    cudaLaunchConfig_t cfg = {};
    cfg.gridDim  = dim3(NB * NB * NB, 1, 1);
    cfg.blockDim = dim3(256, 1, 1);
    cudaLaunchAttribute attrs[1];
    attrs[0].id = cudaLaunchAttributeProgrammaticStreamSerialization;
    attrs[0].val.programmaticStreamSerializationAllowed = 1;
    cfg.attrs = attrs;
    cfg.numAttrs = 1;
    cudaLaunchKernelEx(&cfg, kmain, out);
}